// round 3
// baseline (speedup 1.0000x reference)
#include <cuda_runtime.h>
#include <cstdint>
#include <math.h>

#define B_ 2
#define H_ 16
#define S_ 2048
#define E_ 64
#define NTOK (B_*S_*H_)            // 65536

// Scratch for projected Q,K,V in [B,H,S,E] layout (48 MB total, static device mem)
__device__ float g_q[B_*H_*S_*E_];
__device__ float g_k[B_*H_*S_*E_];
__device__ float g_v[B_*H_*S_*E_];

// ---------------------------------------------------------------------------
// Exact JAX threefry2x32 for key = (0, 42)  (jax.random.key(42))
// Partitionable counter mode: element i -> counter pair (0, i), output x0^x1.
// ---------------------------------------------------------------------------
__device__ __forceinline__ uint32_t threefry_bits_42(uint32_t c1) {
    const uint32_t ks0 = 0u;
    const uint32_t ks1 = 42u;
    const uint32_t ks2 = 0x1BD11BDAu ^ 0u ^ 42u;   // 0x1BD11BF0
    uint32_t x0 = 0u + ks0;          // counts_hi = 0
    uint32_t x1 = c1 + ks1;
#define TF_R(r) { x0 += x1; x1 = __funnelshift_l(x1, x1, (r)); x1 ^= x0; }
    TF_R(13) TF_R(15) TF_R(26) TF_R(6)
    x0 += ks1; x1 += ks2 + 1u;
    TF_R(17) TF_R(29) TF_R(16) TF_R(24)
    x0 += ks2; x1 += ks0 + 2u;
    TF_R(13) TF_R(15) TF_R(26) TF_R(6)
    x0 += ks0; x1 += ks1 + 3u;
    TF_R(17) TF_R(29) TF_R(16) TF_R(24)
    x0 += ks1; x1 += ks2 + 4u;
    TF_R(13) TF_R(15) TF_R(26) TF_R(6)
    x0 += ks2; x1 += ks0 + 5u;
#undef TF_R
    return x0 ^ x1;                  // 32-bit fold (bits1 ^ bits2)
}

// bits -> uniform in [0,1) exactly like jax.random.uniform (float32 path)
__device__ __forceinline__ float jax_uniform(uint32_t bits) {
    return __uint_as_float((bits >> 9) | 0x3f800000u) - 1.0f;
}

// ---------------------------------------------------------------------------
// Projection: out[b,h,s,e] = sum_d x[b,s,h,d] * W[e,d] + bias[e]
// which: 0->g_q, 1->g_k, 2->g_v
// ---------------------------------------------------------------------------
__global__ __launch_bounds__(256) void proj_kernel(
    const float* __restrict__ x, const float* __restrict__ W,
    const float* __restrict__ bias, int which)
{
    __shared__ float Xs[64][65];
    __shared__ float Ws[64][65];
    __shared__ float bs[64];

    float* out = (which == 0) ? g_q : (which == 1) ? g_k : g_v;

    const int tid = threadIdx.x;
    const int n0  = blockIdx.x * 64;   // first token of this block

    #pragma unroll
    for (int it = 0; it < 4; ++it) {
        int elem = tid * 4 + it * 1024;
        int r = elem >> 6, c = elem & 63;
        float4 w4 = *(const float4*)(W + elem);
        Ws[r][c] = w4.x; Ws[r][c+1] = w4.y; Ws[r][c+2] = w4.z; Ws[r][c+3] = w4.w;
        float4 x4 = *(const float4*)(x + (size_t)n0 * 64 + elem);
        Xs[r][c] = x4.x; Xs[r][c+1] = x4.y; Xs[r][c+2] = x4.z; Xs[r][c+3] = x4.w;
    }
    if (tid < 64) bs[tid] = bias[tid];
    __syncthreads();

    const int tx = tid & 15, ty = tid >> 4;
    float acc[4][4] = {};
    #pragma unroll 8
    for (int d = 0; d < 64; ++d) {
        float a[4], b[4];
        #pragma unroll
        for (int i = 0; i < 4; ++i) a[i] = Xs[ty*4+i][d];
        #pragma unroll
        for (int j = 0; j < 4; ++j) b[j] = Ws[tx*4+j][d];
        #pragma unroll
        for (int i = 0; i < 4; ++i)
            #pragma unroll
            for (int j = 0; j < 4; ++j)
                acc[i][j] = fmaf(a[i], b[j], acc[i][j]);
    }

    #pragma unroll
    for (int i = 0; i < 4; ++i) {
        int n   = n0 + ty*4 + i;
        int b_  = n >> 15;            // n / (S_*H_)
        int rem = n & 32767;
        int s   = rem >> 4;           // / H_
        int h   = n & 15;             // % H_
        float* op = out + ((((size_t)b_ * H_ + h) * S_ + s) << 6);
        #pragma unroll
        for (int j = 0; j < 4; ++j) {
            int e = tx*4 + j;
            op[e] = acc[i][j] + bs[e];
        }
    }
}

// ---------------------------------------------------------------------------
// Flash attention with exact-threefry dropout.
// Block: 256 threads, BM=64 query rows, tiles of 64 keys.
// Dynamic smem layout (floats):
//   Qs[64][65], Ks[64][65], Ss[64][65], Vs[64][64], m_s[64], Z_s[64], f_s[64]
// ---------------------------------------------------------------------------
#define SMEM_FLOATS (4160*3 + 4096 + 192)   // 16768 floats = 67072 B

__global__ __launch_bounds__(256, 3) void attn_kernel(
    const float* __restrict__ mask,
    const float* __restrict__ inv_scale,
    float* __restrict__ out)
{
    extern __shared__ float sm[];
    float (*Qs)[65] = (float(*)[65])(sm);
    float (*Ks)[65] = (float(*)[65])(sm + 4160);
    float (*Ss)[65] = (float(*)[65])(sm + 8320);
    float (*Vs)[64] = (float(*)[64])(sm + 12480);
    float* m_s = sm + 16576;
    float* Z_s = sm + 16640;
    float* f_s = sm + 16704;

    const int tid  = threadIdx.x;
    const int s0   = blockIdx.x * 64;
    const int h    = blockIdx.y;
    const int b    = blockIdx.z;
    const float rscale = 1.0f / inv_scale[0];   // inv_scale = 0.125 -> 8.0 exact

    const float* Qg = g_q + ((((size_t)b * H_ + h) * S_ + s0) << 6);
    const float* Kg = g_k + ((((size_t)b * H_ + h) * S_) << 6);
    const float* Vg = g_v + ((((size_t)b * H_ + h) * S_) << 6);
    const float* Mg = mask + ((size_t)b * S_ + s0) * S_;

    // load Q tile [64][64]
    #pragma unroll
    for (int it = 0; it < 4; ++it) {
        int elem = tid * 4 + it * 1024;
        int r = elem >> 6, c = elem & 63;
        float4 q4 = *(const float4*)(Qg + elem);
        Qs[r][c] = q4.x; Qs[r][c+1] = q4.y; Qs[r][c+2] = q4.z; Qs[r][c+3] = q4.w;
    }
    if (tid < 64) { m_s[tid] = -INFINITY; Z_s[tid] = 0.0f; }

    const int tx = tid & 15, ty = tid >> 4;
    const int lane = tid & 31, warp = tid >> 5;

    float acc[4][4] = {};

    for (int t0 = 0; t0 < S_; t0 += 64) {
        __syncthreads();
        // load K, V tiles; preload mask tile into Ss
        #pragma unroll
        for (int it = 0; it < 4; ++it) {
            int elem = tid * 4 + it * 1024;
            int r = elem >> 6, c = elem & 63;
            float4 k4 = *(const float4*)(Kg + (((size_t)t0) << 6) + elem);
            Ks[r][c] = k4.x; Ks[r][c+1] = k4.y; Ks[r][c+2] = k4.z; Ks[r][c+3] = k4.w;
            float4 v4 = *(const float4*)(Vg + (((size_t)t0) << 6) + elem);
            *(float4*)&Vs[r][c] = v4;
            float4 m4 = *(const float4*)(Mg + (size_t)r * S_ + t0 + c);
            Ss[r][c] = m4.x; Ss[r][c+1] = m4.y; Ss[r][c+2] = m4.z; Ss[r][c+3] = m4.w;
        }
        __syncthreads();

        // S = (Q K^T) * rscale + mask   (each thread: 4x4 micro-tile)
        {
            float sacc[4][4] = {};
            #pragma unroll 8
            for (int e = 0; e < 64; ++e) {
                float a[4], bb[4];
                #pragma unroll
                for (int i = 0; i < 4; ++i) a[i] = Qs[ty*4+i][e];
                #pragma unroll
                for (int j = 0; j < 4; ++j) bb[j] = Ks[tx*4+j][e];
                #pragma unroll
                for (int i = 0; i < 4; ++i)
                    #pragma unroll
                    for (int j = 0; j < 4; ++j)
                        sacc[i][j] = fmaf(a[i], bb[j], sacc[i][j]);
            }
            #pragma unroll
            for (int i = 0; i < 4; ++i)
                #pragma unroll
                for (int j = 0; j < 4; ++j)
                    Ss[ty*4+i][tx*4+j] = sacc[i][j] * rscale + Ss[ty*4+i][tx*4+j];
        }
        __syncthreads();

        // online softmax + exact threefry dropout; warp owns rows [warp*8, warp*8+8)
        #pragma unroll 1
        for (int k = 0; k < 8; ++k) {
            int r = warp * 8 + k;
            float v0 = Ss[r][lane];
            float v1 = Ss[r][lane + 32];
            float mx = fmaxf(v0, v1);
            #pragma unroll
            for (int off = 16; off; off >>= 1)
                mx = fmaxf(mx, __shfl_xor_sync(0xffffffffu, mx, off));
            float m_old = m_s[r];
            float m_new = fmaxf(m_old, mx);
            float p0 = __expf(v0 - m_new);
            float p1 = __expf(v1 - m_new);
            float zt = p0 + p1;
            #pragma unroll
            for (int off = 16; off; off >>= 1)
                zt += __shfl_xor_sync(0xffffffffu, zt, off);
            if (lane == 0) {
                float f = __expf(m_old - m_new);
                f_s[r] = f;
                Z_s[r] = Z_s[r] * f + zt;
                m_s[r] = m_new;
            }
            // dropout mask: partitionable threefry counter = flat index over (B,H,S,S)
            uint32_t base = (((uint32_t)(b * H_ + h) * (uint32_t)S_
                              + (uint32_t)(s0 + r)) * (uint32_t)S_)
                          + (uint32_t)t0;
            uint32_t bits0 = threefry_bits_42(base + (uint32_t)lane);
            uint32_t bits1 = threefry_bits_42(base + (uint32_t)lane + 32u);
            Ss[r][lane]      = (jax_uniform(bits0) < 0.9f) ? p0 : 0.0f;
            Ss[r][lane + 32] = (jax_uniform(bits1) < 0.9f) ? p1 : 0.0f;
        }
        __syncthreads();

        // PV accumulate: rescale old acc, then acc += P * V
        {
            float f4[4];
            #pragma unroll
            for (int i = 0; i < 4; ++i) f4[i] = f_s[ty*4+i];
            #pragma unroll
            for (int i = 0; i < 4; ++i)
                #pragma unroll
                for (int j = 0; j < 4; ++j)
                    acc[i][j] *= f4[i];
            #pragma unroll 8
            for (int t = 0; t < 64; ++t) {
                float a[4], bb[4];
                #pragma unroll
                for (int i = 0; i < 4; ++i) a[i] = Ss[ty*4+i][t];
                #pragma unroll
                for (int j = 0; j < 4; ++j) bb[j] = Vs[t][tx*4+j];
                #pragma unroll
                for (int i = 0; i < 4; ++i)
                    #pragma unroll
                    for (int j = 0; j < 4; ++j)
                        acc[i][j] = fmaf(a[i], bb[j], acc[i][j]);
            }
        }
    }

    // write: out[b,h,s,d] = acc / (Z * 0.9)
    #pragma unroll
    for (int i = 0; i < 4; ++i) {
        int r = ty*4 + i;
        float invz = 1.0f / (Z_s[r] * 0.9f);
        float* op = out + ((((size_t)b * H_ + h) * S_ + (s0 + r)) << 6);
        #pragma unroll
        for (int j = 0; j < 4; ++j)
            op[tx*4 + j] = acc[i][j] * invz;
    }
}

// ---------------------------------------------------------------------------
extern "C" void kernel_launch(void* const* d_in, const int* in_sizes, int n_in,
                              void* d_out, int out_size)
{
    const float* query     = (const float*)d_in[0];
    const float* key       = (const float*)d_in[1];
    const float* value     = (const float*)d_in[2];
    const float* attn_mask = (const float*)d_in[3];
    const float* inv_scale = (const float*)d_in[4];
    const float* Wq = (const float*)d_in[5];
    const float* bq = (const float*)d_in[6];
    const float* Wk = (const float*)d_in[7];
    const float* bk = (const float*)d_in[8];
    const float* Wv = (const float*)d_in[9];
    const float* bv = (const float*)d_in[10];
    float* out = (float*)d_out;

    const int nblk = NTOK / 64;   // 1024
    proj_kernel<<<nblk, 256>>>(query, Wq, bq, 0);
    proj_kernel<<<nblk, 256>>>(key,   Wk, bk, 1);
    proj_kernel<<<nblk, 256>>>(value, Wv, bv, 2);

    cudaFuncSetAttribute(attn_kernel,
                         cudaFuncAttributeMaxDynamicSharedMemorySize,
                         SMEM_FLOATS * (int)sizeof(float));
    dim3 grid(S_ / 64, H_, B_);
    attn_kernel<<<grid, 256, SMEM_FLOATS * sizeof(float)>>>(attn_mask, inv_scale, out);
}

// round 4
// speedup vs baseline: 1.1744x; 1.1744x over previous
#include <cuda_runtime.h>
#include <cstdint>
#include <math.h>

#define B_ 2
#define H_ 16
#define S_ 2048
#define E_ 64
#define NTOK (B_*S_*H_)            // 65536
#define LDS_ 68                    // smem row stride (floats): 16B-aligned, conflict-light

// Scratch for projected Q,K,V in [B,H,S,E] layout (48 MB total, static device mem)
__device__ float g_q[B_*H_*S_*E_];
__device__ float g_k[B_*H_*S_*E_];
__device__ float g_v[B_*H_*S_*E_];

// ---------------------------------------------------------------------------
// Exact JAX threefry2x32 for key = (0, 42); partitionable counter mode:
// element i -> counter (0, i), output fold x0 ^ x1.
// ---------------------------------------------------------------------------
__device__ __forceinline__ uint32_t threefry_bits_42(uint32_t c1) {
    const uint32_t ks0 = 0u;
    const uint32_t ks1 = 42u;
    const uint32_t ks2 = 0x1BD11BDAu ^ 0u ^ 42u;   // 0x1BD11BF0
    uint32_t x0 = 0u + ks0;
    uint32_t x1 = c1 + ks1;
#define TF_R(r) { x0 += x1; x1 = __funnelshift_l(x1, x1, (r)); x1 ^= x0; }
    TF_R(13) TF_R(15) TF_R(26) TF_R(6)
    x0 += ks1; x1 += ks2 + 1u;
    TF_R(17) TF_R(29) TF_R(16) TF_R(24)
    x0 += ks2; x1 += ks0 + 2u;
    TF_R(13) TF_R(15) TF_R(26) TF_R(6)
    x0 += ks0; x1 += ks1 + 3u;
    TF_R(17) TF_R(29) TF_R(16) TF_R(24)
    x0 += ks1; x1 += ks2 + 4u;
    TF_R(13) TF_R(15) TF_R(26) TF_R(6)
    x0 += ks2; x1 += ks0 + 5u;
#undef TF_R
    return x0 ^ x1;
}

__device__ __forceinline__ float jax_uniform(uint32_t bits) {
    return __uint_as_float((bits >> 9) | 0x3f800000u) - 1.0f;
}

// ---------------------------------------------------------------------------
// Projection: out[b,h,s,e] = sum_d x[b,s,h,d] * W[e,d] + bias[e]
// ---------------------------------------------------------------------------
__global__ __launch_bounds__(256) void proj_kernel(
    const float* __restrict__ x, const float* __restrict__ W,
    const float* __restrict__ bias, int which)
{
    __shared__ float Xs[64][65];
    __shared__ float Ws[64][65];
    __shared__ float bs[64];

    float* out = (which == 0) ? g_q : (which == 1) ? g_k : g_v;

    const int tid = threadIdx.x;
    const int n0  = blockIdx.x * 64;

    #pragma unroll
    for (int it = 0; it < 4; ++it) {
        int elem = tid * 4 + it * 1024;
        int r = elem >> 6, c = elem & 63;
        float4 w4 = *(const float4*)(W + elem);
        Ws[r][c] = w4.x; Ws[r][c+1] = w4.y; Ws[r][c+2] = w4.z; Ws[r][c+3] = w4.w;
        float4 x4 = *(const float4*)(x + (size_t)n0 * 64 + elem);
        Xs[r][c] = x4.x; Xs[r][c+1] = x4.y; Xs[r][c+2] = x4.z; Xs[r][c+3] = x4.w;
    }
    if (tid < 64) bs[tid] = bias[tid];
    __syncthreads();

    const int tx = tid & 15, ty = tid >> 4;
    float acc[4][4] = {};
    #pragma unroll 8
    for (int d = 0; d < 64; ++d) {
        float a[4], b[4];
        #pragma unroll
        for (int i = 0; i < 4; ++i) a[i] = Xs[ty*4+i][d];
        #pragma unroll
        for (int j = 0; j < 4; ++j) b[j] = Ws[tx*4+j][d];
        #pragma unroll
        for (int i = 0; i < 4; ++i)
            #pragma unroll
            for (int j = 0; j < 4; ++j)
                acc[i][j] = fmaf(a[i], b[j], acc[i][j]);
    }

    #pragma unroll
    for (int i = 0; i < 4; ++i) {
        int n   = n0 + ty*4 + i;
        int b_  = n >> 15;
        int rem = n & 32767;
        int s   = rem >> 4;
        int h   = n & 15;
        float* op = out + ((((size_t)b_ * H_ + h) * S_ + s) << 6);
        #pragma unroll
        for (int j = 0; j < 4; ++j) {
            int e = tx*4 + j;
            op[e] = acc[i][j] + bs[e];
        }
    }
}

// ---------------------------------------------------------------------------
// Flash attention, vectorized LDS.128 GEMM phases + ballot-gated threefry.
// 256 threads, BM=64 query rows, BN=64 key tiles, stride-68 smem rows.
// ---------------------------------------------------------------------------
#define SMEM_FLOATS (4*64*LDS_ + 192)   // Qs,Ks,Ss,Vs + m/Z/f = 17600 floats

__global__ __launch_bounds__(256, 2) void attn_kernel(
    const float* __restrict__ mask,
    const float* __restrict__ inv_scale,
    float* __restrict__ out)
{
    extern __shared__ float sm[];
    float* Qs = sm;
    float* Ks = sm + 64*LDS_;
    float* Ss = sm + 2*64*LDS_;
    float* Vs = sm + 3*64*LDS_;
    float* m_s = sm + 4*64*LDS_;
    float* Z_s = m_s + 64;
    float* f_s = Z_s + 64;

    const int tid  = threadIdx.x;
    const int s0   = blockIdx.x * 64;
    const int h    = blockIdx.y;
    const int b    = blockIdx.z;
    const float rscale = 1.0f / inv_scale[0];

    const float* Qg = g_q + ((((size_t)b * H_ + h) * S_ + s0) << 6);
    const float* Kg = g_k + ((((size_t)b * H_ + h) * S_) << 6);
    const float* Vg = g_v + ((((size_t)b * H_ + h) * S_) << 6);
    const float* Mg = mask + ((size_t)b * S_ + s0) * S_;

    // load Q tile [64][64] -> stride-68 rows
    #pragma unroll
    for (int it = 0; it < 4; ++it) {
        int elem = tid * 4 + it * 1024;
        int r = elem >> 6, c = elem & 63;
        *(float4*)&Qs[r*LDS_ + c] = *(const float4*)(Qg + elem);
    }
    if (tid < 64) { m_s[tid] = -INFINITY; Z_s[tid] = 0.0f; }

    const int tx = tid & 15, ty = tid >> 4;
    const int lane = tid & 31, warp = tid >> 5;

    float acc[4][4] = {};   // output cols 4*tx+j

    for (int t0 = 0; t0 < S_; t0 += 64) {
        __syncthreads();
        #pragma unroll
        for (int it = 0; it < 4; ++it) {
            int elem = tid * 4 + it * 1024;
            int r = elem >> 6, c = elem & 63;
            *(float4*)&Ks[r*LDS_ + c] = *(const float4*)(Kg + (((size_t)t0) << 6) + elem);
            *(float4*)&Vs[r*LDS_ + c] = *(const float4*)(Vg + (((size_t)t0) << 6) + elem);
            *(float4*)&Ss[r*LDS_ + c] = *(const float4*)(Mg + (size_t)r * S_ + t0 + c);
        }
        __syncthreads();

        // S[4ty+i][tx+16j] = (Q K^T)*rscale + mask ; vectorized over e
        {
            float sacc[4][4] = {};
            #pragma unroll
            for (int e = 0; e < 64; e += 4) {
                float4 qv[4], kv[4];
                #pragma unroll
                for (int i = 0; i < 4; ++i)
                    qv[i] = *(const float4*)&Qs[(4*ty+i)*LDS_ + e];
                #pragma unroll
                for (int j = 0; j < 4; ++j)
                    kv[j] = *(const float4*)&Ks[(tx+16*j)*LDS_ + e];
                #pragma unroll
                for (int i = 0; i < 4; ++i)
                    #pragma unroll
                    for (int j = 0; j < 4; ++j) {
                        sacc[i][j] = fmaf(qv[i].x, kv[j].x, sacc[i][j]);
                        sacc[i][j] = fmaf(qv[i].y, kv[j].y, sacc[i][j]);
                        sacc[i][j] = fmaf(qv[i].z, kv[j].z, sacc[i][j]);
                        sacc[i][j] = fmaf(qv[i].w, kv[j].w, sacc[i][j]);
                    }
            }
            #pragma unroll
            for (int i = 0; i < 4; ++i)
                #pragma unroll
                for (int j = 0; j < 4; ++j) {
                    int idx = (4*ty+i)*LDS_ + tx + 16*j;
                    Ss[idx] = fmaf(sacc[i][j], rscale, Ss[idx]);
                }
        }
        __syncthreads();

        // online softmax + ballot-gated exact threefry dropout
        #pragma unroll 1
        for (int k = 0; k < 8; ++k) {
            int r = warp * 8 + k;
            float v0 = Ss[r*LDS_ + lane];
            float v1 = Ss[r*LDS_ + lane + 32];
            float mx = fmaxf(v0, v1);
            #pragma unroll
            for (int off = 16; off; off >>= 1)
                mx = fmaxf(mx, __shfl_xor_sync(0xffffffffu, mx, off));
            float m_old = m_s[r];
            float m_new = fmaxf(m_old, mx);
            float p0 = __expf(v0 - m_new);
            float p1 = __expf(v1 - m_new);
            float zt = p0 + p1;
            #pragma unroll
            for (int off = 16; off; off >>= 1)
                zt += __shfl_xor_sync(0xffffffffu, zt, off);
            if (lane == 0) {
                float f = __expf(m_old - m_new);
                f_s[r] = f;
                Z_s[r] = Z_s[r] * f + zt;
                m_s[r] = m_new;
            }
            // Gate: elements with p < 1e-10 contribute < 1e-10|v| whether
            // dropped or kept -> skip RNG when the whole tile-row is negligible.
            unsigned bal = __ballot_sync(0xffffffffu,
                                         (p0 >= 1e-10f) | (p1 >= 1e-10f));
            if (bal) {
                uint32_t base = (((uint32_t)(b * H_ + h) * (uint32_t)S_
                                  + (uint32_t)(s0 + r)) * (uint32_t)S_)
                              + (uint32_t)t0;
                uint32_t bits0 = threefry_bits_42(base + (uint32_t)lane);
                uint32_t bits1 = threefry_bits_42(base + (uint32_t)lane + 32u);
                Ss[r*LDS_ + lane]      = (jax_uniform(bits0) < 0.9f) ? p0 : 0.0f;
                Ss[r*LDS_ + lane + 32] = (jax_uniform(bits1) < 0.9f) ? p1 : 0.0f;
            } else {
                Ss[r*LDS_ + lane]      = p0;
                Ss[r*LDS_ + lane + 32] = p1;
            }
        }
        __syncthreads();

        // PV accumulate (cols 4tx+j), vectorized over t and j
        {
            float f4[4];
            #pragma unroll
            for (int i = 0; i < 4; ++i) f4[i] = f_s[4*ty+i];
            #pragma unroll
            for (int i = 0; i < 4; ++i)
                #pragma unroll
                for (int j = 0; j < 4; ++j)
                    acc[i][j] *= f4[i];
            #pragma unroll
            for (int t = 0; t < 64; t += 4) {
                float4 sv[4], vv[4];
                #pragma unroll
                for (int i = 0; i < 4; ++i)
                    sv[i] = *(const float4*)&Ss[(4*ty+i)*LDS_ + t];
                #pragma unroll
                for (int tt = 0; tt < 4; ++tt)
                    vv[tt] = *(const float4*)&Vs[(t+tt)*LDS_ + 4*tx];
                #pragma unroll
                for (int i = 0; i < 4; ++i) {
                    acc[i][0] = fmaf(sv[i].x, vv[0].x, acc[i][0]);
                    acc[i][1] = fmaf(sv[i].x, vv[0].y, acc[i][1]);
                    acc[i][2] = fmaf(sv[i].x, vv[0].z, acc[i][2]);
                    acc[i][3] = fmaf(sv[i].x, vv[0].w, acc[i][3]);
                    acc[i][0] = fmaf(sv[i].y, vv[1].x, acc[i][0]);
                    acc[i][1] = fmaf(sv[i].y, vv[1].y, acc[i][1]);
                    acc[i][2] = fmaf(sv[i].y, vv[1].z, acc[i][2]);
                    acc[i][3] = fmaf(sv[i].y, vv[1].w, acc[i][3]);
                    acc[i][0] = fmaf(sv[i].z, vv[2].x, acc[i][0]);
                    acc[i][1] = fmaf(sv[i].z, vv[2].y, acc[i][1]);
                    acc[i][2] = fmaf(sv[i].z, vv[2].z, acc[i][2]);
                    acc[i][3] = fmaf(sv[i].z, vv[2].w, acc[i][3]);
                    acc[i][0] = fmaf(sv[i].w, vv[3].x, acc[i][0]);
                    acc[i][1] = fmaf(sv[i].w, vv[3].y, acc[i][1]);
                    acc[i][2] = fmaf(sv[i].w, vv[3].z, acc[i][2]);
                    acc[i][3] = fmaf(sv[i].w, vv[3].w, acc[i][3]);
                }
            }
        }
    }

    // write: out[b,h,s,4tx..4tx+3] = acc / (Z * 0.9)   (float4 stores)
    #pragma unroll
    for (int i = 0; i < 4; ++i) {
        int r = 4*ty + i;
        float invz = 1.0f / (Z_s[r] * 0.9f);
        float* op = out + ((((size_t)b * H_ + h) * S_ + (s0 + r)) << 6);
        float4 o4;
        o4.x = acc[i][0] * invz;
        o4.y = acc[i][1] * invz;
        o4.z = acc[i][2] * invz;
        o4.w = acc[i][3] * invz;
        *(float4*)(op + 4*tx) = o4;
    }
}

// ---------------------------------------------------------------------------
extern "C" void kernel_launch(void* const* d_in, const int* in_sizes, int n_in,
                              void* d_out, int out_size)
{
    const float* query     = (const float*)d_in[0];
    const float* key       = (const float*)d_in[1];
    const float* value     = (const float*)d_in[2];
    const float* attn_mask = (const float*)d_in[3];
    const float* inv_scale = (const float*)d_in[4];
    const float* Wq = (const float*)d_in[5];
    const float* bq = (const float*)d_in[6];
    const float* Wk = (const float*)d_in[7];
    const float* bk = (const float*)d_in[8];
    const float* Wv = (const float*)d_in[9];
    const float* bv = (const float*)d_in[10];
    float* out = (float*)d_out;

    const int nblk = NTOK / 64;   // 1024
    proj_kernel<<<nblk, 256>>>(query, Wq, bq, 0);
    proj_kernel<<<nblk, 256>>>(key,   Wk, bk, 1);
    proj_kernel<<<nblk, 256>>>(value, Wv, bv, 2);

    cudaFuncSetAttribute(attn_kernel,
                         cudaFuncAttributeMaxDynamicSharedMemorySize,
                         SMEM_FLOATS * (int)sizeof(float));
    dim3 grid(S_ / 64, H_, B_);
    attn_kernel<<<grid, 256, SMEM_FLOATS * sizeof(float)>>>(attn_mask, inv_scale, out);
}